// round 2
// baseline (speedup 1.0000x reference)
#include <cuda_runtime.h>
#include <cstdint>

// Group_feat_network: N=512 samples, G=60 group elems, K=13 neighbors.
// All comb layers computed as fused-gather tf32 tensor-core GEMMs with
// activations kept in [C, G, N] layout (n contiguous) so gathered A-tile
// rows are contiguous 128-float segments.

#define NPTS 512
#define GDIM 60
#define KNEI 13

// ---------------- scratch (device globals; no allocations allowed) -----------
__device__ float g_xT [32  * GDIM * NPTS];   // feats transposed [c][g][n]
__device__ float g_h  [256 * GDIM * NPTS];   // conv_in output
__device__ float g_r  [512 * GDIM * NPTS];   // relu(comb_r1)
__device__ float g_h2 [256 * GDIM * NPTS];   // h + comb_r2
__device__ float g_e  [32  * GDIM * NPTS];   // comb_out + feats (pre-norm eqv)
__device__ float g_Wt_in [32  * KNEI * 256];
__device__ float g_Wt_r1 [256 * KNEI * 512];
__device__ float g_Wt_r2 [512 * KNEI * 256];
__device__ float g_Wt_out[256 * KNEI * 32];

// ---------------- helpers ----------------------------------------------------
static __device__ __forceinline__ uint32_t f2tf32(float x) {
    uint32_t r;
    asm("cvt.rna.tf32.f32 %0, %1;" : "=r"(r) : "f"(x));
    return r;
}

static __device__ __forceinline__ void mma_tf32(float* d, const uint32_t* a, const uint32_t* b) {
    asm volatile(
        "mma.sync.aligned.m16n8k8.row.col.f32.tf32.tf32.f32 "
        "{%0,%1,%2,%3}, {%4,%5,%6,%7}, {%8,%9}, {%0,%1,%2,%3};\n"
        : "+f"(d[0]), "+f"(d[1]), "+f"(d[2]), "+f"(d[3])
        : "r"(a[0]), "r"(a[1]), "r"(a[2]), "r"(a[3]),
          "r"(b[0]), "r"(b[1]));
}

// ---------------- layout transforms ------------------------------------------
// feats [N,32,G] (row-major) -> xT [32][G][N]
__global__ void transpose_x(const float* __restrict__ f, float* __restrict__ xT) {
    int idx = blockIdx.x * blockDim.x + threadIdx.x;
    if (idx >= 32 * GDIM * NPTS) return;
    int n  = idx & (NPTS - 1);
    int gg = idx >> 9;            // c*60 + g
    int g  = gg % GDIM;
    int c  = gg / GDIM;
    xT[idx] = f[(n * 32 + c) * GDIM + g];
}

// W [O,C,13] -> Wt [(c*13+k)][O]
__global__ void transpose_w(const float* __restrict__ W, float* __restrict__ Wt,
                            int O, int C) {
    int idx = blockIdx.x * blockDim.x + threadIdx.x;
    int total = O * C * KNEI;
    if (idx >= total) return;
    int o  = idx % O;
    int ck = idx / O;
    int c  = ck / KNEI;
    int k  = ck - c * KNEI;
    Wt[idx] = W[(o * C + c) * KNEI + k];
}

// ---------------- fused-gather GEMM ------------------------------------------
// out[o][g][n] = bias[o] + sum_{c,k} W[o,c,k] * xT[c][nei[g*13+k]][n]
// EPI: 0 = bias only, 1 = bias+relu, 2 = bias + residual(res at same index)
template<int CIN, int OOUT, int BN, int EPI>
__global__ void __launch_bounds__(256) comb_gemm(
    const float* __restrict__ xT, const float* __restrict__ Wt,
    const float* __restrict__ bias, const int* __restrict__ nei,
    const float* __restrict__ res, float* __restrict__ out)
{
    constexpr int KK = CIN * KNEI;
    constexpr int BM = 128, BK = 16;
    constexpr int WARPS_N = (BN >= 128) ? 4 : 1;
    constexpr int WARPS_M = 8 / WARPS_N;
    constexpr int WM = BM / WARPS_M;
    constexpr int WN = BN / WARPS_N;
    constexpr int MI = WM / 16;
    constexpr int NI = WN / 8;
    constexpr int LDA = BM + 4;     // pad: conflict-free frag loads
    constexpr int LDB = BN + 4;
    constexpr int A_THR = BM * BK / 256;
    constexpr int B_THR = BN * BK / 256;

    __shared__ uint32_t As[BK][LDA];
    __shared__ uint32_t Bs[BK][LDB];
    __shared__ int s_joff[KNEI];

    const int g   = blockIdx.z;
    const int m0  = blockIdx.x * BM;
    const int n0  = blockIdx.y * BN;
    const int tid = threadIdx.x;
    const int lane = tid & 31;
    const int warp = tid >> 5;
    const int wm = warp % WARPS_M;
    const int wn = warp / WARPS_M;
    const int qid = lane >> 2;
    const int rid = lane & 3;

    if (tid < KNEI) s_joff[tid] = nei[g * KNEI + tid];
    __syncthreads();

    float acc[MI][NI][4];
    #pragma unroll
    for (int i = 0; i < MI; i++)
        #pragma unroll
        for (int j = 0; j < NI; j++)
            #pragma unroll
            for (int v = 0; v < 4; v++) acc[i][j][v] = 0.f;

    float ra[A_THR], rb[B_THR];

    auto loadA = [&](int kk) {
        #pragma unroll
        for (int i = 0; i < A_THR; i++) {
            int idx = tid + i * 256;
            int row = idx / BM;
            int col = idx % BM;
            int ck = kk + row;
            int c = ck / KNEI;
            int k = ck - c * KNEI;
            ra[i] = xT[(c * GDIM + s_joff[k]) * NPTS + m0 + col];
        }
    };
    auto loadB = [&](int kk) {
        #pragma unroll
        for (int i = 0; i < B_THR; i++) {
            int idx = tid + i * 256;
            int row = idx / BN;
            int col = idx % BN;
            rb[i] = Wt[(kk + row) * OOUT + n0 + col];
        }
    };
    auto store = [&]() {
        #pragma unroll
        for (int i = 0; i < A_THR; i++) {
            int idx = tid + i * 256;
            As[idx / BM][idx % BM] = f2tf32(ra[i]);
        }
        #pragma unroll
        for (int i = 0; i < B_THR; i++) {
            int idx = tid + i * 256;
            Bs[idx / BN][idx % BN] = f2tf32(rb[i]);
        }
    };
    auto compute = [&]() {
        #pragma unroll
        for (int ks = 0; ks < 2; ks++) {
            const int k0 = ks * 8;
            uint32_t af[MI][4], bf[NI][2];
            #pragma unroll
            for (int mi = 0; mi < MI; mi++) {
                int m = wm * WM + mi * 16 + qid;
                af[mi][0] = As[k0 + rid][m];
                af[mi][1] = As[k0 + rid][m + 8];
                af[mi][2] = As[k0 + rid + 4][m];
                af[mi][3] = As[k0 + rid + 4][m + 8];
            }
            #pragma unroll
            for (int ni = 0; ni < NI; ni++) {
                int n = wn * WN + ni * 8 + qid;
                bf[ni][0] = Bs[k0 + rid][n];
                bf[ni][1] = Bs[k0 + rid + 4][n];
            }
            #pragma unroll
            for (int mi = 0; mi < MI; mi++)
                #pragma unroll
                for (int ni = 0; ni < NI; ni++)
                    mma_tf32(acc[mi][ni], af[mi], bf[ni]);
        }
    };

    loadA(0); loadB(0);
    store();
    __syncthreads();
    for (int kk = BK; kk < KK; kk += BK) {
        loadA(kk); loadB(kk);   // prefetch into registers
        compute();              // consume current SMEM tiles
        __syncthreads();
        store();
        __syncthreads();
    }
    compute();

    // ---- epilogue: bias (+relu | +residual), write [o][g][n] ----
    #pragma unroll
    for (int mi = 0; mi < MI; mi++) {
        #pragma unroll
        for (int ni = 0; ni < NI; ni++) {
            int row = wm * WM + mi * 16 + qid;
            int col = wn * WN + ni * 8 + 2 * rid;
            #pragma unroll
            for (int v = 0; v < 4; v++) {
                int rr = row + ((v >= 2) ? 8 : 0);
                int cc = col + (v & 1);
                int o  = n0 + cc;
                float val = acc[mi][ni][v] + bias[o];
                if (EPI == 1) val = fmaxf(val, 0.f);
                int idx = o * (GDIM * NPTS) + g * NPTS + m0 + rr;
                if (EPI == 2) val += res[idx];
                out[idx] = val;
            }
        }
    }
}

// ---------------- final normalization ----------------------------------------
// e [32][60][512] -> out: feats_inv [512][32] then feats_eqv [512][32][60]
__global__ void finalize(const float* __restrict__ e, float* __restrict__ out) {
    const int n = blockIdx.x;
    __shared__ float es[32][65];
    const int tid = threadIdx.x;   // blockDim = 64

    if (tid < GDIM) {
        #pragma unroll
        for (int c = 0; c < 32; c++)
            es[c][tid] = e[(c * GDIM + tid) * NPTS + n];
    }
    __syncthreads();

    if (tid < GDIM) {
        float s = 0.f;
        #pragma unroll
        for (int c = 0; c < 32; c++) s += es[c][tid] * es[c][tid];
        float inv = 1.f / fmaxf(sqrtf(s), 1e-4f);
        #pragma unroll
        for (int c = 0; c < 32; c++)
            out[NPTS * 32 + n * (32 * GDIM) + c * GDIM + tid] = es[c][tid] * inv;
    }

    if (tid < 32) {   // warp 0 entirely
        float s = 0.f;
        #pragma unroll
        for (int g = 0; g < GDIM; g++) s += es[tid][g];
        float m = s * (1.f / 60.f);
        float sq = m * m;
        #pragma unroll
        for (int off = 16; off; off >>= 1)
            sq += __shfl_xor_sync(0xffffffffu, sq, off);
        float nrm = fmaxf(sqrtf(sq), 1e-4f);
        out[n * 32 + tid] = m / nrm;
    }
}

// ---------------- launch ------------------------------------------------------
extern "C" void kernel_launch(void* const* d_in, const int* in_sizes, int n_in,
                              void* d_out, int out_size) {
    const float* feats = (const float*)d_in[0];
    const int*   nei   = (const int*)  d_in[1];
    const float* W_in  = (const float*)d_in[2];
    const float* b_in  = (const float*)d_in[3];
    const float* W_r1  = (const float*)d_in[4];
    const float* b_r1  = (const float*)d_in[5];
    const float* W_r2  = (const float*)d_in[6];
    const float* b_r2  = (const float*)d_in[7];
    const float* W_out = (const float*)d_in[8];
    const float* b_out = (const float*)d_in[9];
    float* out = (float*)d_out;

    void *xT, *h, *r, *h2, *e, *wi, *w1, *w2, *wo;
    cudaGetSymbolAddress(&xT, g_xT);
    cudaGetSymbolAddress(&h,  g_h);
    cudaGetSymbolAddress(&r,  g_r);
    cudaGetSymbolAddress(&h2, g_h2);
    cudaGetSymbolAddress(&e,  g_e);
    cudaGetSymbolAddress(&wi, g_Wt_in);
    cudaGetSymbolAddress(&w1, g_Wt_r1);
    cudaGetSymbolAddress(&w2, g_Wt_r2);
    cudaGetSymbolAddress(&wo, g_Wt_out);

    transpose_x<<<(32 * GDIM * NPTS + 255) / 256, 256>>>(feats, (float*)xT);
    transpose_w<<<(256 * 32  * KNEI + 255) / 256, 256>>>(W_in,  (float*)wi, 256, 32);
    transpose_w<<<(512 * 256 * KNEI + 255) / 256, 256>>>(W_r1,  (float*)w1, 512, 256);
    transpose_w<<<(256 * 512 * KNEI + 255) / 256, 256>>>(W_r2,  (float*)w2, 256, 512);
    transpose_w<<<(32  * 256 * KNEI + 255) / 256, 256>>>(W_out, (float*)wo, 32, 256);

    // conv_in: 32 -> 256
    comb_gemm<32, 256, 128, 0><<<dim3(4, 2, GDIM), 256>>>(
        (const float*)xT, (const float*)wi, b_in, nei, nullptr, (float*)h);
    // r = relu(comb_r1(h)): 256 -> 512
    comb_gemm<256, 512, 128, 1><<<dim3(4, 4, GDIM), 256>>>(
        (const float*)h, (const float*)w1, b_r1, nei, nullptr, (float*)r);
    // h2 = h + comb_r2(r): 512 -> 256
    comb_gemm<512, 256, 128, 2><<<dim3(4, 2, GDIM), 256>>>(
        (const float*)r, (const float*)w2, b_r2, nei, (const float*)h, (float*)h2);
    // e = comb_out(h2) + feats: 256 -> 32
    comb_gemm<256, 32, 32, 2><<<dim3(4, 1, GDIM), 256>>>(
        (const float*)h2, (const float*)wo, b_out, nei, (const float*)xT, (float*)e);

    finalize<<<NPTS, 64>>>((const float*)e, out);
}

// round 16
// speedup vs baseline: 1.9920x; 1.9920x over previous
#include <cuda_runtime.h>
#include <cstdint>

#define NPTS 512
#define GDIM 60
#define KNEI 13
#define BKK  32
#define NSTG 3

// ---------------- scratch (device globals; no allocations allowed) -----------
// activations in [c][g][n] layout (n contiguous).  _t = tf32-RNA-rounded copy.
__device__ float g_xT_f[32  * GDIM * NPTS];
__device__ float g_xT_t[32  * GDIM * NPTS];
__device__ float g_h_f [256 * GDIM * NPTS];
__device__ float g_h_t [256 * GDIM * NPTS];
__device__ float g_r_t [512 * GDIM * NPTS];
__device__ float g_h2_t[256 * GDIM * NPTS];
__device__ float g_e   [32  * GDIM * NPTS];
// weights reordered to [(c*13+k)][O], tf32-rounded
__device__ float g_W0[32  * KNEI * 256];
__device__ float g_W1[256 * KNEI * 512];
__device__ float g_W2[512 * KNEI * 256];
__device__ float g_W3[256 * KNEI * 32];

// ---------------- helpers ----------------------------------------------------
static __device__ __forceinline__ float f2tf32f(float x) {
    uint32_t r;
    asm("cvt.rna.tf32.f32 %0, %1;" : "=r"(r) : "f"(x));
    return __uint_as_float(r);
}
static __device__ __forceinline__ uint32_t smaddr(const void* p) {
    uint32_t a;
    asm("{ .reg .u64 t; cvta.to.shared.u64 t, %1; cvt.u32.u64 %0, t; }" : "=r"(a) : "l"(p));
    return a;
}
static __device__ __forceinline__ void cp16(uint32_t dst, const float* src) {
    asm volatile("cp.async.cg.shared.global [%0], [%1], 16;" :: "r"(dst), "l"(src));
}
static __device__ __forceinline__ void cp_commit() {
    asm volatile("cp.async.commit_group;" ::: "memory");
}
template<int N> static __device__ __forceinline__ void cp_wait() {
    asm volatile("cp.async.wait_group %0;" :: "n"(N) : "memory");
}
static __device__ __forceinline__ void mma_tf32(float* d, const uint32_t* a, const uint32_t* b) {
    asm volatile(
        "mma.sync.aligned.m16n8k8.row.col.f32.tf32.tf32.f32 "
        "{%0,%1,%2,%3}, {%4,%5,%6,%7}, {%8,%9}, {%0,%1,%2,%3};\n"
        : "+f"(d[0]), "+f"(d[1]), "+f"(d[2]), "+f"(d[3])
        : "r"(a[0]), "r"(a[1]), "r"(a[2]), "r"(a[3]),
          "r"(b[0]), "r"(b[1]));
}

// ---------------- layout transforms ------------------------------------------
// feats [N,32,G] -> xT [c][g][n] (full + rounded)
__global__ void reorder_x(const float* __restrict__ f,
                          float* __restrict__ xf, float* __restrict__ xt) {
    int idx = blockIdx.x * blockDim.x + threadIdx.x;
    if (idx >= 32 * GDIM * NPTS) return;
    int n  = idx & (NPTS - 1);
    int gg = idx >> 9;
    int g  = gg % GDIM;
    int c  = gg / GDIM;
    float v = f[(n * 32 + c) * GDIM + g];
    xf[idx] = v;
    xt[idx] = f2tf32f(v);
}
// W [O,C,13] -> Wt [(c*13+k)][O], rounded
__global__ void reorder_w(const float* __restrict__ W, float* __restrict__ Wt,
                          int O, int C) {
    int idx = blockIdx.x * blockDim.x + threadIdx.x;
    if (idx >= O * C * KNEI) return;
    int o  = idx % O;
    int ck = idx / O;
    int c  = ck / KNEI;
    int k  = ck - c * KNEI;
    Wt[idx] = f2tf32f(W[(o * C + c) * KNEI + k]);
}

// ---------------- fused-gather GEMM (cp.async + mma.sync tf32) ----------------
// out[o][g][n] = bias[o] + sum_{c,k} W[o,c,k] * A[c][nei[g*13+k]][n]
// EPI: 0 bias | 1 bias+relu | 2 bias+residual.  WF/WT: write full / rounded.
template<int CIN, int OOUT, int BN, int EPI, int WF, int WT>
__global__ void __launch_bounds__(256, 1) comb_gemm(
    const float* __restrict__ A, const float* __restrict__ Wt,
    const float* __restrict__ bias, const int* __restrict__ nei,
    const float* __restrict__ res,
    float* __restrict__ outF, float* __restrict__ outT)
{
    constexpr int BM = 128;
    constexpr int KK = CIN * KNEI;
    constexpr int NC = KK / BKK;
    constexpr int WARPS_N = (BN >= 256) ? 4 : 1;
    constexpr int WARPS_M = 8 / WARPS_N;
    constexpr int WM = BM / WARPS_M;      // 64 or 16
    constexpr int WN = BN / WARPS_N;      // 64 or 32
    constexpr int MI = WM / 16;
    constexpr int NI = WN / 8;
    constexpr int LDA = BM + 8;           // +8 floats: 16B aligned, conflict-free frags
    constexpr int LDB = BN + 8;
    constexpr int A_CH = BKK * BM / 4 / 256;   // 16B chunks per thread
    constexpr int B_CH = BKK * BN / 4 / 256;
    constexpr int A_STG = BKK * LDA;
    constexpr int B_STG = BKK * LDB;

    extern __shared__ float sm[];
    float* Asm = sm;
    float* Bsm = sm + NSTG * A_STG;
    __shared__ int joff[KNEI];

    const int tid  = threadIdx.x;
    const int lane = tid & 31;
    const int warp = tid >> 5;
    const int wm   = warp % WARPS_M;
    const int wn   = warp / WARPS_M;
    const int qid  = lane >> 2;
    const int rid  = lane & 3;
    const int g    = blockIdx.z;
    const int m0   = blockIdx.x * BM;
    const int n0   = blockIdx.y * BN;

    if (tid < KNEI) joff[tid] = nei[g * KNEI + tid];
    __syncthreads();

    auto prefetch = [&](int ch) {
        const int s = ch % NSTG;
        float* as = Asm + s * A_STG;
        float* bs = Bsm + s * B_STG;
        #pragma unroll
        for (int i = 0; i < A_CH; i++) {
            int idx = tid + i * 256;
            int row = idx / (BM / 4);
            int col = (idx % (BM / 4)) * 4;
            int ck  = ch * BKK + row;
            int c   = ck / KNEI;
            int k   = ck - c * KNEI;
            const float* gp = A + (size_t)(c * GDIM + joff[k]) * NPTS + m0 + col;
            cp16(smaddr(as + row * LDA + col), gp);
        }
        #pragma unroll
        for (int i = 0; i < B_CH; i++) {
            int idx = tid + i * 256;
            int row = idx / (BN / 4);
            int col = (idx % (BN / 4)) * 4;
            const float* gp = Wt + (size_t)(ch * BKK + row) * OOUT + n0 + col;
            cp16(smaddr(bs + row * LDB + col), gp);
        }
    };

    float acc[MI][NI][4];
    #pragma unroll
    for (int i = 0; i < MI; i++)
        #pragma unroll
        for (int j = 0; j < NI; j++)
            #pragma unroll
            for (int v = 0; v < 4; v++) acc[i][j][v] = 0.f;

    // initial NSTG-1 prefetches
    #pragma unroll
    for (int s = 0; s < NSTG - 1; s++) { prefetch(s); cp_commit(); }

    for (int it = 0; it < NC; it++) {
        cp_wait<NSTG - 2>();
        __syncthreads();
        // refill the slot freed at the previous barrier
        if (it + NSTG - 1 < NC) prefetch(it + NSTG - 1);
        cp_commit();

        const int s = it % NSTG;
        const float* as = Asm + s * A_STG + wm * WM;
        const float* bs = Bsm + s * B_STG + wn * WN;
        #pragma unroll
        for (int ks = 0; ks < BKK / 8; ks++) {
            const int k0 = ks * 8;
            uint32_t af[MI][4], bf[NI][2];
            #pragma unroll
            for (int mi = 0; mi < MI; mi++) {
                int m = mi * 16 + qid;
                af[mi][0] = __float_as_uint(as[(k0 + rid) * LDA + m]);
                af[mi][1] = __float_as_uint(as[(k0 + rid) * LDA + m + 8]);
                af[mi][2] = __float_as_uint(as[(k0 + rid + 4) * LDA + m]);
                af[mi][3] = __float_as_uint(as[(k0 + rid + 4) * LDA + m + 8]);
            }
            #pragma unroll
            for (int ni = 0; ni < NI; ni++) {
                int n = ni * 8 + qid;
                bf[ni][0] = __float_as_uint(bs[(k0 + rid) * LDB + n]);
                bf[ni][1] = __float_as_uint(bs[(k0 + rid + 4) * LDB + n]);
            }
            #pragma unroll
            for (int mi = 0; mi < MI; mi++)
                #pragma unroll
                for (int ni = 0; ni < NI; ni++)
                    mma_tf32(acc[mi][ni], af[mi], bf[ni]);
        }
    }

    // ---- epilogue ----
    #pragma unroll
    for (int mi = 0; mi < MI; mi++) {
        #pragma unroll
        for (int ni = 0; ni < NI; ni++) {
            #pragma unroll
            for (int v = 0; v < 4; v++) {
                int row = wm * WM + mi * 16 + qid + ((v >= 2) ? 8 : 0);
                int col = wn * WN + ni * 8 + 2 * rid + (v & 1);
                int o   = n0 + col;
                float val = acc[mi][ni][v] + bias[o];
                if (EPI == 1) val = fmaxf(val, 0.f);
                size_t idx = (size_t)o * (GDIM * NPTS) + (size_t)g * NPTS + m0 + row;
                if (EPI == 2) val += res[idx];
                if (WF) outF[idx] = val;
                if (WT) outT[idx] = f2tf32f(val);
            }
        }
    }
}

// ---------------- final normalization ----------------------------------------
// e [c][g][n] -> out: feats_inv [512,32] then feats_eqv [512,32,60]
__global__ void finalize(const float* __restrict__ e, float* __restrict__ out) {
    const int n = blockIdx.x;
    __shared__ float es[32][65];
    const int tid = threadIdx.x;   // blockDim = 64

    if (tid < GDIM) {
        #pragma unroll
        for (int c = 0; c < 32; c++)
            es[c][tid] = e[(c * GDIM + tid) * NPTS + n];
    }
    __syncthreads();

    if (tid < GDIM) {
        float s = 0.f;
        #pragma unroll
        for (int c = 0; c < 32; c++) s += es[c][tid] * es[c][tid];
        float inv = 1.f / fmaxf(sqrtf(s), 1e-4f);
        #pragma unroll
        for (int c = 0; c < 32; c++)
            out[NPTS * 32 + n * (32 * GDIM) + c * GDIM + tid] = es[c][tid] * inv;
    }

    if (tid < 32) {
        float s = 0.f;
        #pragma unroll
        for (int g = 0; g < GDIM; g++) s += es[tid][g];
        float m = s * (1.f / 60.f);
        float sq = m * m;
        #pragma unroll
        for (int off = 16; off; off >>= 1)
            sq += __shfl_xor_sync(0xffffffffu, sq, off);
        float nrm = fmaxf(sqrtf(sq), 1e-4f);
        out[n * 32 + tid] = m / nrm;
    }
}

// ---------------- launch ------------------------------------------------------
static inline int smem_bytes(int BN) {
    return NSTG * (BKK * (128 + 8) + BKK * (BN + 8)) * 4;
}

extern "C" void kernel_launch(void* const* d_in, const int* in_sizes, int n_in,
                              void* d_out, int out_size) {
    const float* feats = (const float*)d_in[0];
    const int*   nei   = (const int*)  d_in[1];
    const float* W_in  = (const float*)d_in[2];
    const float* b_in  = (const float*)d_in[3];
    const float* W_r1  = (const float*)d_in[4];
    const float* b_r1  = (const float*)d_in[5];
    const float* W_r2  = (const float*)d_in[6];
    const float* b_r2  = (const float*)d_in[7];
    const float* W_out = (const float*)d_in[8];
    const float* b_out = (const float*)d_in[9];
    float* out = (float*)d_out;

    void *xf, *xt, *hf, *ht, *rt, *h2t, *e, *w0, *w1, *w2, *w3;
    cudaGetSymbolAddress(&xf,  g_xT_f);
    cudaGetSymbolAddress(&xt,  g_xT_t);
    cudaGetSymbolAddress(&hf,  g_h_f);
    cudaGetSymbolAddress(&ht,  g_h_t);
    cudaGetSymbolAddress(&rt,  g_r_t);
    cudaGetSymbolAddress(&h2t, g_h2_t);
    cudaGetSymbolAddress(&e,   g_e);
    cudaGetSymbolAddress(&w0,  g_W0);
    cudaGetSymbolAddress(&w1,  g_W1);
    cudaGetSymbolAddress(&w2,  g_W2);
    cudaGetSymbolAddress(&w3,  g_W3);

    reorder_x<<<(32 * GDIM * NPTS + 255) / 256, 256>>>(feats, (float*)xf, (float*)xt);
    reorder_w<<<(256 * 32  * KNEI + 255) / 256, 256>>>(W_in,  (float*)w0, 256, 32);
    reorder_w<<<(512 * 256 * KNEI + 255) / 256, 256>>>(W_r1,  (float*)w1, 512, 256);
    reorder_w<<<(256 * 512 * KNEI + 255) / 256, 256>>>(W_r2,  (float*)w2, 256, 512);
    reorder_w<<<(32  * 256 * KNEI + 255) / 256, 256>>>(W_out, (float*)w3, 32, 256);

    cudaFuncSetAttribute(comb_gemm<32, 256, 256, 0, 1, 1>,
                         cudaFuncAttributeMaxDynamicSharedMemorySize, smem_bytes(256));
    cudaFuncSetAttribute(comb_gemm<256, 512, 256, 1, 0, 1>,
                         cudaFuncAttributeMaxDynamicSharedMemorySize, smem_bytes(256));
    cudaFuncSetAttribute(comb_gemm<512, 256, 256, 2, 0, 1>,
                         cudaFuncAttributeMaxDynamicSharedMemorySize, smem_bytes(256));
    cudaFuncSetAttribute(comb_gemm<256, 32, 32, 2, 1, 0>,
                         cudaFuncAttributeMaxDynamicSharedMemorySize, smem_bytes(32));

    // L0: conv_in 32 -> 256 (h full + rounded)
    comb_gemm<32, 256, 256, 0, 1, 1><<<dim3(4, 1, GDIM), 256, smem_bytes(256)>>>(
        (const float*)xt, (const float*)w0, b_in, nei, nullptr,
        (float*)hf, (float*)ht);
    // L1: r = relu(comb_r1(h)) 256 -> 512 (rounded only)
    comb_gemm<256, 512, 256, 1, 0, 1><<<dim3(4, 2, GDIM), 256, smem_bytes(256)>>>(
        (const float*)ht, (const float*)w1, b_r1, nei, nullptr,
        nullptr, (float*)rt);
    // L2: h2 = h + comb_r2(r) 512 -> 256 (rounded only; residual = h full)
    comb_gemm<512, 256, 256, 2, 0, 1><<<dim3(4, 1, GDIM), 256, smem_bytes(256)>>>(
        (const float*)rt, (const float*)w2, b_r2, nei, (const float*)hf,
        nullptr, (float*)h2t);
    // L3: e = comb_out(h2) + feats 256 -> 32 (full only; residual = xT full)
    comb_gemm<256, 32, 32, 2, 1, 0><<<dim3(4, 1, GDIM), 256, smem_bytes(32)>>>(
        (const float*)h2t, (const float*)w3, b_out, nei, (const float*)xf,
        (float*)e, nullptr);

    finalize<<<NPTS, 64>>>((const float*)e, out);
}